// round 6
// baseline (speedup 1.0000x reference)
#include <cuda_runtime.h>
#include <cstdint>

#define FULLMASK 0xFFFFFFFFu
typedef unsigned long long ULL;

static constexpr int L = 64;
static constexpr int H = 32;
static constexpr int B = 1024;
static constexpr float LOG2E = 1.4426950408889634f;
static constexpr float LN2   = 0.6931471805599453f;

__device__ __forceinline__ ULL pack2(float lo, float hi) {
    ULL r; asm("mov.b64 %0, {%1, %2};" : "=l"(r) : "f"(lo), "f"(hi)); return r;
}
__device__ __forceinline__ void unpack2(ULL v, float& lo, float& hi) {
    asm("mov.b64 {%0, %1}, %2;" : "=f"(lo), "=f"(hi) : "l"(v));
}
__device__ __forceinline__ ULL ffma2(ULL a, ULL b, ULL c) {
    ULL d; asm("fma.rn.f32x2 %0, %1, %2, %3;" : "=l"(d) : "l"(a), "l"(b), "l"(c)); return d;
}
__device__ __forceinline__ ULL fadd2(ULL a, ULL b) {
    ULL d; asm("add.rn.f32x2 %0, %1, %2;" : "=l"(d) : "l"(a), "l"(b)); return d;
}
__device__ __forceinline__ float ex2f(float x) {
    float r; asm("ex2.approx.f32 %0, %1;" : "=f"(r) : "f"(x)); return r;
}
// ELU(alpha=1) on a log2-scaled pre-activation p2 = pre * log2(e).
__device__ __forceinline__ float elu2(float p2) {
    return fmaxf(p2 * LN2, 0.f) + (ex2f(fminf(p2, 0.f)) - 1.f);
}

__global__ void __launch_bounds__(32)
rnn2d_kernel(const int* __restrict__ x,        // [B, L, L] in {0,1}
             const float* __restrict__ Win,    // [4, H]
             const float* __restrict__ WcH,    // [H, H]
             const float* __restrict__ WcV,    // [H, H]
             const float* __restrict__ bV,     // [H]
             const float* __restrict__ Wout,   // [H, 2]
             const float* __restrict__ bout,   // [2]
             float* __restrict__ out)          // [B]
{
    __shared__ __align__(16) float hrow[L * H];  // [c][lane]: h of current row
    __shared__ __align__(16) float vbuf[L * H];  // [c][lane]: vertical pre-act (log2-scaled)
    __shared__ int xrow[2][L];
    __shared__ __align__(16) float dws[H];

    const int lane = threadIdx.x;
    const int sample = blockIdx.x;

    // ---- per-lane weights (recurrence weights pre-scaled by log2e) ----
    const float win0 = Win[0 * H + lane] * LOG2E;
    const float win1 = Win[1 * H + lane] * LOG2E;
    const float win2 = Win[2 * H + lane] * LOG2E;
    const float win3 = Win[3 * H + lane] * LOG2E;
    const float bv   = bV[lane] * LOG2E;
    const float dbo  = bout[0] - bout[1];
    dws[lane] = Wout[lane * 2 + 0] - Wout[lane * 2 + 1];

    ULL wch[16], wcv[16];
    #pragma unroll
    for (int k = 0; k < 16; k++) {
        wch[k] = pack2(WcH[(2 * k) * H + lane] * LOG2E, WcH[(2 * k + 1) * H + lane] * LOG2E);
        wcv[k] = pack2(WcV[(2 * k) * H + lane] * LOG2E, WcV[(2 * k + 1) * H + lane] * LOG2E);
    }

    const int* xs = x + (long)sample * (L * L);

    // Row 0 x, and vbuf for row 0 (cV = 0, stateV = 0 -> bias + stateH only).
    xrow[0][lane]      = xs[lane];
    xrow[0][lane + 32] = xs[lane + 32];
    __syncwarp();
    {
        float wa = 0.f;
        #pragma unroll 4
        for (int c = 0; c < L; c++) {
            vbuf[(c << 5) + lane] = bv + wa;
            wa = xrow[0][c] ? win1 : win0;
        }
    }

    ULL hA[16], hB[16];           // double-buffered replicated h
    float logacc = 0.f;
    int c0 = 0, dir = 1;

    for (int r = 0; r < L; r++) {
        const int cur = r & 1, nxt = cur ^ 1;

        // Order prev row's head reads (hrow/xrow) before this row's writes.
        __syncwarp();
        const int rl = (r < L - 1) ? r + 1 : r;      // clamp (last row: harmless)
        xrow[nxt][lane]      = xs[rl * L + lane];
        xrow[nxt][lane + 32] = xs[rl * L + lane + 32];
        __syncwarp();

        int c = c0;

        // ---- step 0 (no horizontal carry): fill hA with h(c0) ----
        {
            const float h = elu2(vbuf[(c << 5) + lane]);
            hrow[(c << 5) + lane] = h;
            __syncwarp();
            const ulonglong2* hp = reinterpret_cast<const ulonglong2*>(hrow + (c << 5));
            #pragma unroll
            for (int k = 0; k < 8; k++) {
                ulonglong2 v = hp[k];
                hA[2 * k] = v.x; hA[2 * k + 1] = v.y;
            }
        }
        float vpre = vbuf[((c + dir) << 5) + lane];
        int xc = xrow[cur][c];
        int xn = xrow[nxt][c + dir];

        // ---- pipelined fused step: hOld = h(c); computes h(cn) into hNew,
        //      and produce(c) from hOld under the LDS shadow. ----
        auto fused = [&](ULL* hOld, ULL* hNew) {
            const int cn = c + dir;
            // WcH matvec on hOld -> pre(cn)
            ULL a0 = pack2(vpre, 0.f), a1 = 0ull, a2 = 0ull, a3 = 0ull;
            #pragma unroll
            for (int k = 0; k < 16; k += 4) {
                a0 = ffma2(hOld[k + 0], wch[k + 0], a0);
                a1 = ffma2(hOld[k + 1], wch[k + 1], a1);
                a2 = ffma2(hOld[k + 2], wch[k + 2], a2);
                a3 = ffma2(hOld[k + 3], wch[k + 3], a3);
            }
            a0 = fadd2(a0, a1);
            a2 = fadd2(a2, a3);
            a0 = fadd2(a0, a2);
            float lo, hi; unpack2(a0, lo, hi);
            const float h = elu2(lo + hi);
            hrow[(cn << 5) + lane] = h;
            __syncwarp();

            // Issue the broadcast loads FIRST (into the other buffer), then
            // hide their latency under the WcV produce-matvec on hOld.
            {
                const ulonglong2* hp = reinterpret_cast<const ulonglong2*>(hrow + (cn << 5));
                #pragma unroll
                for (int k = 0; k < 8; k++) {
                    ulonglong2 v = hp[k];
                    hNew[2 * k] = v.x; hNew[2 * k + 1] = v.y;
                }
            }
            const float rsum = bv + (xn ? win1 : win0) + (xc ? win3 : win2);
            ULL v0 = pack2(rsum, 0.f), v1 = 0ull, v2 = 0ull, v3 = 0ull;
            #pragma unroll
            for (int k = 0; k < 16; k += 4) {
                v0 = ffma2(hOld[k + 0], wcv[k + 0], v0);
                v1 = ffma2(hOld[k + 1], wcv[k + 1], v1);
                v2 = ffma2(hOld[k + 2], wcv[k + 2], v2);
                v3 = ffma2(hOld[k + 3], wcv[k + 3], v3);
            }
            v0 = fadd2(v0, v1);
            v2 = fadd2(v2, v3);
            v0 = fadd2(v0, v2);
            float vl, vh; unpack2(v0, vl, vh);
            vbuf[(c << 5) + lane] = vl + vh;   // produce(c): own-lane slot

            // Prefetch next-iteration operands.
            int cn2 = cn + dir;
            cn2 = (cn2 < 0) ? 0 : ((cn2 > L - 1) ? L - 1 : cn2);   // clamp; stale ok
            vpre = vbuf[(cn2 << 5) + lane];
            xc = xrow[cur][cn];
            xn = xrow[nxt][cn2];
            c = cn;
        };

        // 63 steps: 31 double-iterations + final one. Parity keeps buffers straight.
        #pragma unroll 1
        for (int j = 0; j < 31; j++) {
            fused(hA, hB);
            fused(hB, hA);
        }
        fused(hA, hB);     // final: current h lives in hB

        // ---- epilogue: produce(c_last) — next row starts here, no stateH ----
        {
            ULL v0 = pack2(bv + (xc ? win3 : win2), 0.f), v1 = 0ull, v2 = 0ull, v3 = 0ull;
            #pragma unroll
            for (int k = 0; k < 16; k += 4) {
                v0 = ffma2(hB[k + 0], wcv[k + 0], v0);
                v1 = ffma2(hB[k + 1], wcv[k + 1], v1);
                v2 = ffma2(hB[k + 2], wcv[k + 2], v2);
                v3 = ffma2(hB[k + 3], wcv[k + 3], v3);
            }
            v0 = fadd2(v0, v1);
            v2 = fadd2(v2, v3);
            v0 = fadd2(v0, v2);
            float vl, vh; unpack2(v0, vl, vh);
            vbuf[(c << 5) + lane] = vl + vh;
        }

        // ---- row-batched output head: lane handles columns lane, lane+32 ----
        #pragma unroll
        for (int t = 0; t < 2; t++) {
            const int cc = lane + 32 * t;
            const ulonglong2* hcol = reinterpret_cast<const ulonglong2*>(hrow + (cc << 5));
            const ulonglong2* dwp  = reinterpret_cast<const ulonglong2*>(dws);
            ULL q0 = 0ull, q1 = 0ull;
            #pragma unroll
            for (int k = 0; k < 8; k++) {
                const int kk = (k + lane) & 7;   // bank-rotate
                ulonglong2 hv = hcol[kk];
                ulonglong2 dv = dwp[kk];
                q0 = ffma2(hv.x, dv.x, q0);
                q1 = ffma2(hv.y, dv.y, q1);
            }
            q0 = fadd2(q0, q1);
            float lo, hi; unpack2(q0, lo, hi);
            const float q = lo + hi + dbo;
            const float tt = xrow[cur][cc] ? q : -q;
            logacc -= fmaxf(tt, 0.f) + __logf(1.f + __expf(-fabsf(tt)));
        }

        c0 = c;          // snake: next row starts where this one ended
        dir = -dir;
    }

    #pragma unroll
    for (int off = 16; off; off >>= 1)
        logacc += __shfl_xor_sync(FULLMASK, logacc, off);
    if (lane == 0) out[sample] = 0.5f * logacc;
}

extern "C" void kernel_launch(void* const* d_in, const int* in_sizes, int n_in,
                              void* d_out, int out_size)
{
    const int*   x    = (const int*)  d_in[0];
    const float* Win  = (const float*)d_in[1];
    const float* WcH  = (const float*)d_in[2];
    const float* WcV  = (const float*)d_in[3];
    const float* bV   = (const float*)d_in[4];
    const float* Wout = (const float*)d_in[5];
    const float* bout = (const float*)d_in[6];
    float* out = (float*)d_out;

    rnn2d_kernel<<<B, 32>>>(x, Win, WcH, WcV, bV, Wout, bout, out);
}

// round 7
// speedup vs baseline: 1.1089x; 1.1089x over previous
#include <cuda_runtime.h>
#include <cstdint>

#define FULLMASK 0xFFFFFFFFu
typedef unsigned long long ULL;

static constexpr int L = 64;
static constexpr int H = 32;
static constexpr int B = 1024;
static constexpr float LOG2E = 1.4426950408889634f;
static constexpr float LN2   = 0.6931471805599453f;

__device__ __forceinline__ ULL pack2(float lo, float hi) {
    ULL r; asm("mov.b64 %0, {%1, %2};" : "=l"(r) : "f"(lo), "f"(hi)); return r;
}
__device__ __forceinline__ void unpack2(ULL v, float& lo, float& hi) {
    asm("mov.b64 {%0, %1}, %2;" : "=f"(lo), "=f"(hi) : "l"(v));
}
__device__ __forceinline__ ULL ffma2(ULL a, ULL b, ULL c) {
    ULL d; asm("fma.rn.f32x2 %0, %1, %2, %3;" : "=l"(d) : "l"(a), "l"(b), "l"(c)); return d;
}
__device__ __forceinline__ ULL fadd2(ULL a, ULL b) {
    ULL d; asm("add.rn.f32x2 %0, %1, %2;" : "=l"(d) : "l"(a), "l"(b)); return d;
}
__device__ __forceinline__ float ex2f(float x) {
    float r; asm("ex2.approx.f32 %0, %1;" : "=f"(r) : "f"(x)); return r;
}
// h' = ELU(pre)+1 from log2-scaled pre-activation p2 = pre*log2e.
// h' = max(p2,0)*ln2 + ex2(min(p2,0))   (no -1: folded into rowsum constants)
__device__ __forceinline__ float eluP1(float p2) {
    return fmaxf(p2, 0.f) * LN2 + ex2f(fminf(p2, 0.f));
}

__global__ void __launch_bounds__(32)
rnn2d_kernel(const int* __restrict__ x,        // [B, L, L] in {0,1}
             const float* __restrict__ Win,    // [4, H]
             const float* __restrict__ WcH,    // [H, H]
             const float* __restrict__ WcV,    // [H, H]
             const float* __restrict__ bV,     // [H]
             const float* __restrict__ Wout,   // [H, 2]
             const float* __restrict__ bout,   // [2]
             float* __restrict__ out)          // [B]
{
    __shared__ __align__(16) float hrow[L * H];  // [c][lane]: h' of current row
    __shared__ __align__(16) float vbuf[L * H];  // [c][lane]: vertical pre-act (log2-scaled, folded)
    __shared__ int xrow[2][L];
    __shared__ __align__(16) float dws[H];

    const int lane = threadIdx.x;
    const int sample = blockIdx.x;

    // ---- per-lane weights (recurrence weights pre-scaled by log2e) ----
    const float win0 = Win[0 * H + lane] * LOG2E;
    const float win1 = Win[1 * H + lane] * LOG2E;
    const float win2 = Win[2 * H + lane] * LOG2E;
    const float win3 = Win[3 * H + lane] * LOG2E;
    const float bv   = bV[lane] * LOG2E;
    const float dwsl = Wout[lane * 2 + 0] - Wout[lane * 2 + 1];
    dws[lane] = dwsl;

    ULL wch[16], wcv[16];
    float rowsumH = 0.f, rowsumV = 0.f;   // sum_i W[i][lane] (scaled)
    #pragma unroll
    for (int k = 0; k < 16; k++) {
        const float h0 = WcH[(2 * k) * H + lane] * LOG2E;
        const float h1 = WcH[(2 * k + 1) * H + lane] * LOG2E;
        const float v0 = WcV[(2 * k) * H + lane] * LOG2E;
        const float v1 = WcV[(2 * k + 1) * H + lane] * LOG2E;
        wch[k] = pack2(h0, h1);
        wcv[k] = pack2(v0, v1);
        rowsumH += h0 + h1;
        rowsumV += v0 + v1;
    }
    // head bias fold: q = sum h'[i]dws[i] + (dbo - sum dws[i])
    float sdws = dwsl;
    #pragma unroll
    for (int off = 16; off; off >>= 1)
        sdws += __shfl_xor_sync(FULLMASK, sdws, off);
    const float dbo = (bout[0] - bout[1]) - sdws;

    // Folded produce bases:
    const float base_main = bv - rowsumV - rowsumH;  // consumed as vpre (has WcH term)
    const float base_epi  = bv - rowsumV;            // consumed as row-start seed (no WcH)

    const int* xs = x + (long)sample * (L * L);

    // Row 0 x, and vbuf for row 0 (cV=0, stateV=0; h'-folds: only WcH fold applies).
    xrow[0][lane]      = xs[lane];
    xrow[0][lane + 32] = xs[lane + 32];
    __syncwarp();
    {
        float wa = 0.f;
        #pragma unroll 4
        for (int c = 0; c < L; c++) {
            vbuf[(c << 5) + lane] = ((c == 0) ? bv : (bv - rowsumH)) + wa;
            wa = xrow[0][c] ? win1 : win0;
        }
    }

    ULL hA[16], hB[16];           // double-buffered replicated h'
    float logacc = 0.f;
    int c0 = 0, dir = 1;

    for (int r = 0; r < L; r++) {
        const int cur = r & 1, nxt = cur ^ 1;

        // Order prev row's head reads (hrow/xrow) before this row's writes.
        __syncwarp();
        const int rl = (r < L - 1) ? r + 1 : r;
        xrow[nxt][lane]      = xs[rl * L + lane];
        xrow[nxt][lane + 32] = xs[rl * L + lane + 32];
        __syncwarp();

        int c = c0;

        // ---- step 0 (no horizontal carry): fill hA with h'(c0) ----
        {
            const float h = eluP1(vbuf[(c << 5) + lane]);
            hrow[(c << 5) + lane] = h;
            // same-warp converged STS->LDS: in-order LSU, no sync needed
            const ulonglong2* hp = reinterpret_cast<const ulonglong2*>(hrow + (c << 5));
            #pragma unroll
            for (int k = 0; k < 8; k++) {
                ulonglong2 v = hp[k];
                hA[2 * k] = v.x; hA[2 * k + 1] = v.y;
            }
        }
        float vpre = vbuf[((c + dir) << 5) + lane];
        int xc = xrow[cur][c];
        int xn = xrow[nxt][c + dir];

        // ---- fused step: hOld = h'(c); compute h'(cn) into hNew; produce(c). ----
        auto fused = [&](ULL* hOld, ULL* hNew) {
            const int cn = c + dir;
            // WcH matvec on hOld -> pre(cn). (vpre seeds chain a0; prefetched early.)
            ULL a0 = pack2(vpre, 0.f), a1 = 0ull, a2 = 0ull, a3 = 0ull;
            #pragma unroll
            for (int k = 0; k < 16; k += 4) {
                a0 = ffma2(hOld[k + 0], wch[k + 0], a0);
                a1 = ffma2(hOld[k + 1], wch[k + 1], a1);
                a2 = ffma2(hOld[k + 2], wch[k + 2], a2);
                a3 = ffma2(hOld[k + 3], wch[k + 3], a3);
            }
            a0 = fadd2(a0, a1);
            a2 = fadd2(a2, a3);
            a0 = fadd2(a0, a2);
            float lo, hi; unpack2(a0, lo, hi);
            const float h = eluP1(lo + hi);
            hrow[(cn << 5) + lane] = h;

            // LDS burst immediately (same-warp STS->LDS ordering, no sync), then
            // all prefetches, then produce fills the load-latency window.
            {
                const ulonglong2* hp = reinterpret_cast<const ulonglong2*>(hrow + (cn << 5));
                #pragma unroll
                for (int k = 0; k < 8; k++) {
                    ulonglong2 v = hp[k];
                    hNew[2 * k] = v.x; hNew[2 * k + 1] = v.y;
                }
            }
            int cn2 = cn + dir;
            cn2 = (cn2 < 0) ? 0 : ((cn2 > L - 1) ? L - 1 : cn2);   // clamp; stale ok
            const float vpre2 = vbuf[(cn2 << 5) + lane];
            const int xc2 = xrow[cur][cn];
            const int xn2 = xrow[nxt][cn2];

            // produce(c) on hOld (off the chain; fills hNew load window)
            const float rsum = base_main + (xn ? win1 : win0) + (xc ? win3 : win2);
            ULL v0 = pack2(rsum, 0.f), v1 = 0ull, v2 = 0ull, v3 = 0ull;
            #pragma unroll
            for (int k = 0; k < 16; k += 4) {
                v0 = ffma2(hOld[k + 0], wcv[k + 0], v0);
                v1 = ffma2(hOld[k + 1], wcv[k + 1], v1);
                v2 = ffma2(hOld[k + 2], wcv[k + 2], v2);
                v3 = ffma2(hOld[k + 3], wcv[k + 3], v3);
            }
            v0 = fadd2(v0, v1);
            v2 = fadd2(v2, v3);
            v0 = fadd2(v0, v2);
            float vl, vh; unpack2(v0, vl, vh);
            vbuf[(c << 5) + lane] = vl + vh;   // own-lane slot

            vpre = vpre2; xc = xc2; xn = xn2;
            c = cn;
        };

        #pragma unroll 1
        for (int j = 0; j < 31; j++) {
            fused(hA, hB);
            fused(hB, hA);
        }
        fused(hA, hB);     // final: current h' lives in hB

        // ---- epilogue: produce(c_last) — consumed as next row's seed (no WcH fold) ----
        {
            ULL v0 = pack2(base_epi + (xc ? win3 : win2), 0.f), v1 = 0ull, v2 = 0ull, v3 = 0ull;
            #pragma unroll
            for (int k = 0; k < 16; k += 4) {
                v0 = ffma2(hB[k + 0], wcv[k + 0], v0);
                v1 = ffma2(hB[k + 1], wcv[k + 1], v1);
                v2 = ffma2(hB[k + 2], wcv[k + 2], v2);
                v3 = ffma2(hB[k + 3], wcv[k + 3], v3);
            }
            v0 = fadd2(v0, v1);
            v2 = fadd2(v2, v3);
            v0 = fadd2(v0, v2);
            float vl, vh; unpack2(v0, vl, vh);
            vbuf[(c << 5) + lane] = vl + vh;
        }

        // Cross-lane hrow reads below need all lanes' stores visible.
        __syncwarp();

        // ---- row-batched output head: lane handles columns lane, lane+32 ----
        #pragma unroll
        for (int t = 0; t < 2; t++) {
            const int cc = lane + 32 * t;
            const ulonglong2* hcol = reinterpret_cast<const ulonglong2*>(hrow + (cc << 5));
            const ulonglong2* dwp  = reinterpret_cast<const ulonglong2*>(dws);
            ULL q0 = 0ull, q1 = 0ull;
            #pragma unroll
            for (int k = 0; k < 8; k++) {
                const int kk = (k + lane) & 7;   // bank-rotate
                ulonglong2 hv = hcol[kk];
                ulonglong2 dv = dwp[kk];
                q0 = ffma2(hv.x, dv.x, q0);
                q1 = ffma2(hv.y, dv.y, q1);
            }
            q0 = fadd2(q0, q1);
            float lo, hi; unpack2(q0, lo, hi);
            const float q = lo + hi + dbo;      // dbo already has -sum(dws) fold
            const float tt = xrow[cur][cc] ? q : -q;
            logacc -= fmaxf(tt, 0.f) + __logf(1.f + __expf(-fabsf(tt)));
        }

        c0 = c;          // snake: next row starts where this one ended
        dir = -dir;
    }

    #pragma unroll
    for (int off = 16; off; off >>= 1)
        logacc += __shfl_xor_sync(FULLMASK, logacc, off);
    if (lane == 0) out[sample] = 0.5f * logacc;
}

extern "C" void kernel_launch(void* const* d_in, const int* in_sizes, int n_in,
                              void* d_out, int out_size)
{
    const int*   x    = (const int*)  d_in[0];
    const float* Win  = (const float*)d_in[1];
    const float* WcH  = (const float*)d_in[2];
    const float* WcV  = (const float*)d_in[3];
    const float* bV   = (const float*)d_in[4];
    const float* Wout = (const float*)d_in[5];
    const float* bout = (const float*)d_in[6];
    float* out = (float*)d_out;

    rnn2d_kernel<<<B, 32>>>(x, Win, WcH, WcV, bV, Wout, bout, out);
}

// round 9
// speedup vs baseline: 1.1580x; 1.0443x over previous
#include <cuda_runtime.h>
#include <cstdint>

#define FULLMASK 0xFFFFFFFFu
typedef unsigned long long ULL;

static constexpr int L = 64;
static constexpr int H = 32;
static constexpr int B = 1024;
static constexpr float LOG2E = 1.4426950408889634f;
static constexpr float LN2   = 0.6931471805599453f;

__device__ __forceinline__ ULL pack2(float lo, float hi) {
    ULL r; asm("mov.b64 %0, {%1, %2};" : "=l"(r) : "f"(lo), "f"(hi)); return r;
}
__device__ __forceinline__ void unpack2(ULL v, float& lo, float& hi) {
    asm("mov.b64 {%0, %1}, %2;" : "=f"(lo), "=f"(hi) : "l"(v));
}
__device__ __forceinline__ ULL ffma2(ULL a, ULL b, ULL c) {
    ULL d; asm("fma.rn.f32x2 %0, %1, %2, %3;" : "=l"(d) : "l"(a), "l"(b), "l"(c)); return d;
}
__device__ __forceinline__ ULL fadd2(ULL a, ULL b) {
    ULL d; asm("add.rn.f32x2 %0, %1, %2;" : "=l"(d) : "l"(a), "l"(b)); return d;
}
__device__ __forceinline__ float ex2f(float x) {
    float r; asm("ex2.approx.f32 %0, %1;" : "=f"(r) : "f"(x)); return r;
}
// h' = ELU(pre)+1 from log2-scaled pre-activation p2 = pre*log2e.
__device__ __forceinline__ float eluP1(float p2) {
    return fmaxf(p2, 0.f) * LN2 + ex2f(fminf(p2, 0.f));
}

__global__ void __launch_bounds__(32)
rnn2d_kernel(const int* __restrict__ x,        // [B, L, L] in {0,1}
             const float* __restrict__ Win,    // [4, H]
             const float* __restrict__ WcH,    // [H, H]
             const float* __restrict__ WcV,    // [H, H]
             const float* __restrict__ bV,     // [H]
             const float* __restrict__ Wout,   // [H, 2]
             const float* __restrict__ bout,   // [2]
             float* __restrict__ out)          // [B]
{
    __shared__ __align__(16) float hrow[L * H];   // [c][lane]: h' of current row
    __shared__ __align__(16) ULL   vbufP[L * H];  // [c][lane]: vertical pre-act PAIR
    __shared__ __align__(16) float xrf[2][L];     // x rows as float
    __shared__ __align__(16) float dws[H];

    const int lane = threadIdx.x;
    const int sample = blockIdx.x;

    // ---- per-lane weights (recurrence weights pre-scaled by log2e) ----
    const float win0 = Win[0 * H + lane] * LOG2E;
    const float win1 = Win[1 * H + lane] * LOG2E;
    const float win2 = Win[2 * H + lane] * LOG2E;
    const float win3 = Win[3 * H + lane] * LOG2E;
    const float d01  = win1 - win0;
    const float d23  = win3 - win2;
    const float bv   = bV[lane] * LOG2E;
    const float dwsl = Wout[lane * 2 + 0] - Wout[lane * 2 + 1];
    dws[lane] = dwsl;

    ULL wch[16], wcv[16];
    float rowsumH = 0.f, rowsumV = 0.f;
    #pragma unroll
    for (int k = 0; k < 16; k++) {
        const float h0 = WcH[(2 * k) * H + lane] * LOG2E;
        const float h1 = WcH[(2 * k + 1) * H + lane] * LOG2E;
        const float v0 = WcV[(2 * k) * H + lane] * LOG2E;
        const float v1 = WcV[(2 * k + 1) * H + lane] * LOG2E;
        wch[k] = pack2(h0, h1);
        wcv[k] = pack2(v0, v1);
        rowsumH += h0 + h1;
        rowsumV += v0 + v1;
    }
    float sdws = dwsl;
    #pragma unroll
    for (int off = 16; off; off >>= 1)
        sdws += __shfl_xor_sync(FULLMASK, sdws, off);
    const float dbo = (bout[0] - bout[1]) - sdws;    // head bias with h'=h+1 fold

    // Folded produce bases (x-independent parts pre-added):
    const float cbase_main = bv - rowsumV - rowsumH + win0 + win2;
    const float cbase_epi  = bv - rowsumV + win2;

    const int* xs = x + (long)sample * (L * L);

    // Row 0 x as float, and vbuf pairs for row 0 (cV=0, stateV=0).
    xrf[0][lane]      = (float)xs[lane];
    xrf[0][lane + 32] = (float)xs[lane + 32];
    __syncwarp();
    {
        vbufP[lane] = pack2(bv, 0.f);                       // c = 0: no WcH fold
        const float b0 = bv - rowsumH + win0;
        #pragma unroll 4
        for (int c = 1; c < L; c++)
            vbufP[(c << 5) + lane] = pack2(fmaf(xrf[0][c - 1], d01, b0), 0.f);
    }

    ULL hA[16], hB[16];
    float logacc = 0.f;
    int c0 = 0, dir = 1;

    for (int r = 0; r < L; r++) {
        const int cur = r & 1, nxt = cur ^ 1;

        __syncwarp();
        const int rl = (r < L - 1) ? r + 1 : r;
        xrf[nxt][lane]      = (float)xs[rl * L + lane];
        xrf[nxt][lane + 32] = (float)xs[rl * L + lane + 32];
        __syncwarp();

        auto rowbody = [&](const int DIR) {
            float* hcol = hrow + (c0 << 5);                       // column base
            ULL*   vwr  = vbufP + (c0 << 5) + lane;               // produce write
            const ULL* vrd = vbufP + ((c0 + 2 * DIR) << 5) + lane;// vpre prefetch
            const float* xcp = xrf[cur] + c0 + DIR;               // xc prefetch
            const float* xnp = xrf[nxt] + c0 + 2 * DIR;           // xn prefetch

            // ---- step 0 (no horizontal carry): h'(c0) into hA ----
            {
                float lo, hi; unpack2(vwr[0], lo, hi);
                const float h = eluP1(lo + hi);
                hcol[lane] = h;
                const ulonglong2* hp = reinterpret_cast<const ulonglong2*>(hcol);
                #pragma unroll
                for (int k = 0; k < 8; k++) {
                    ulonglong2 v = hp[k];
                    hA[2 * k] = v.x; hA[2 * k + 1] = v.y;
                }
            }
            ULL   vpre = *(vbufP + ((c0 + DIR) << 5) + lane);
            float xcf  = xrf[cur][c0];
            float xnf  = xrf[nxt][c0 + DIR];

            // ---- fused step: h'(cn) from hOld; produce(c) from hOld ----
            auto fused = [&](ULL* hOld, ULL* hNew, const bool PF) {
                float* hc = hcol + DIR * H;
                // WcH matvec seeded by the vpre pair
                ULL a0 = vpre, a1 = 0ull, a2 = 0ull, a3 = 0ull;
                #pragma unroll
                for (int k = 0; k < 16; k += 4) {
                    a0 = ffma2(hOld[k + 0], wch[k + 0], a0);
                    a1 = ffma2(hOld[k + 1], wch[k + 1], a1);
                    a2 = ffma2(hOld[k + 2], wch[k + 2], a2);
                    a3 = ffma2(hOld[k + 3], wch[k + 3], a3);
                }
                a0 = fadd2(a0, a1);
                a2 = fadd2(a2, a3);
                a0 = fadd2(a0, a2);
                float lo, hi; unpack2(a0, lo, hi);
                const float h = eluP1(lo + hi);
                hc[lane] = h;
                // LDS burst immediately (same-warp STS->LDS order, no sync)
                {
                    const ulonglong2* hp = reinterpret_cast<const ulonglong2*>(hc);
                    #pragma unroll
                    for (int k = 0; k < 8; k++) {
                        ulonglong2 v = hp[k];
                        hNew[2 * k] = v.x; hNew[2 * k + 1] = v.y;
                    }
                }
                // prefetches (fill the load window)
                ULL vpre2 = 0ull; float xnf2 = 0.f;
                if (PF) { vpre2 = *vrd; vrd += DIR * H; xnf2 = *xnp; xnp += DIR; }
                const float xcf2 = *xcp; xcp += DIR;

                // produce(c) on hOld: rsum via FMA-selects, 2 chains, pair store
                const float rsum = fmaf(xcf, d23, fmaf(xnf, d01, cbase_main));
                ULL v0 = pack2(rsum, 0.f), v1 = 0ull;
                #pragma unroll
                for (int k = 0; k < 16; k += 2) {
                    v0 = ffma2(hOld[k + 0], wcv[k + 0], v0);
                    v1 = ffma2(hOld[k + 1], wcv[k + 1], v1);
                }
                *vwr = fadd2(v0, v1);
                vwr += DIR * H;

                if (PF) { vpre = vpre2; xnf = xnf2; }
                xcf = xcf2;
                hcol = hc;
            };

            #pragma unroll 1
            for (int j = 0; j < 31; j++) {
                fused(hA, hB, true);
                fused(hB, hA, true);
            }
            fused(hA, hB, false);       // final: no out-of-range prefetch

            // ---- epilogue: produce(c_last) — next row's start seed (no stateH) ----
            {
                const float rsum = fmaf(xcf, d23, cbase_epi);
                ULL v0 = pack2(rsum, 0.f), v1 = 0ull;
                #pragma unroll
                for (int k = 0; k < 16; k += 2) {
                    v0 = ffma2(hB[k + 0], wcv[k + 0], v0);
                    v1 = ffma2(hB[k + 1], wcv[k + 1], v1);
                }
                *vwr = fadd2(v0, v1);
            }
        };

        if (dir > 0) rowbody(1); else rowbody(-1);

        __syncwarp();   // cross-lane hrow reads below

        // ---- row-batched output head: lane handles columns lane, lane+32 ----
        #pragma unroll
        for (int t = 0; t < 2; t++) {
            const int cc = lane + 32 * t;
            const ulonglong2* hcolp = reinterpret_cast<const ulonglong2*>(hrow + (cc << 5));
            const ulonglong2* dwp   = reinterpret_cast<const ulonglong2*>(dws);
            ULL q0 = 0ull, q1 = 0ull;
            #pragma unroll
            for (int k = 0; k < 8; k++) {
                const int kk = (k + lane) & 7;   // bank-rotate
                ulonglong2 hv = hcolp[kk];
                ulonglong2 dv = dwp[kk];
                q0 = ffma2(hv.x, dv.x, q0);
                q1 = ffma2(hv.y, dv.y, q1);
            }
            q0 = fadd2(q0, q1);
            float lo, hi; unpack2(q0, lo, hi);
            const float q = lo + hi + dbo;
            const float tt = (xrf[cur][cc] > 0.5f) ? q : -q;
            logacc -= fmaxf(tt, 0.f) + __logf(1.f + __expf(-fabsf(tt)));
        }

        c0 += 63 * dir;     // snake: next row starts where this one ended
        dir = -dir;
    }

    #pragma unroll
    for (int off = 16; off; off >>= 1)
        logacc += __shfl_xor_sync(FULLMASK, logacc, off);
    if (lane == 0) out[sample] = 0.5f * logacc;
}

extern "C" void kernel_launch(void* const* d_in, const int* in_sizes, int n_in,
                              void* d_out, int out_size)
{
    const int*   x    = (const int*)  d_in[0];
    const float* Win  = (const float*)d_in[1];
    const float* WcH  = (const float*)d_in[2];
    const float* WcV  = (const float*)d_in[3];
    const float* bV   = (const float*)d_in[4];
    const float* Wout = (const float*)d_in[5];
    const float* bout = (const float*)d_in[6];
    float* out = (float*)d_out;

    rnn2d_kernel<<<B, 32>>>(x, Win, WcH, WcV, bV, Wout, bout, out);
}

// round 10
// speedup vs baseline: 1.1749x; 1.0146x over previous
#include <cuda_runtime.h>
#include <cstdint>

#define FULLMASK 0xFFFFFFFFu
typedef unsigned long long ULL;

static constexpr int L = 64;
static constexpr int H = 32;
static constexpr int B = 1024;
static constexpr float LOG2E = 1.4426950408889634f;
static constexpr float LN2   = 0.6931471805599453f;

__device__ __forceinline__ ULL pack2(float lo, float hi) {
    ULL r; asm("mov.b64 %0, {%1, %2};" : "=l"(r) : "f"(lo), "f"(hi)); return r;
}
__device__ __forceinline__ void unpack2(ULL v, float& lo, float& hi) {
    asm("mov.b64 {%0, %1}, %2;" : "=f"(lo), "=f"(hi) : "l"(v));
}
__device__ __forceinline__ ULL ffma2(ULL a, ULL b, ULL c) {
    ULL d; asm("fma.rn.f32x2 %0, %1, %2, %3;" : "=l"(d) : "l"(a), "l"(b), "l"(c)); return d;
}
__device__ __forceinline__ ULL fadd2(ULL a, ULL b) {
    ULL d; asm("add.rn.f32x2 %0, %1, %2;" : "=l"(d) : "l"(a), "l"(b)); return d;
}
__device__ __forceinline__ float ex2f(float x) {
    float r; asm("ex2.approx.f32 %0, %1;" : "=f"(r) : "f"(x)); return r;
}
// h' = ELU(pre)+1 from log2-scaled pre-activation p2 = pre*log2e.
__device__ __forceinline__ float eluP1(float p2) {
    return fmaf(fmaxf(p2, 0.f), LN2, ex2f(fminf(p2, 0.f)));
}

__global__ void __launch_bounds__(32)
rnn2d_kernel(const int* __restrict__ x,        // [B, L, L] in {0,1}
             const float* __restrict__ Win,    // [4, H]
             const float* __restrict__ WcH,    // [H, H]
             const float* __restrict__ WcV,    // [H, H]
             const float* __restrict__ bV,     // [H]
             const float* __restrict__ Wout,   // [H, 2]
             const float* __restrict__ bout,   // [2]
             float* __restrict__ out)          // [B]
{
    __shared__ __align__(16) float  hrow[L * H];   // [c][lane]: h' of current row
    __shared__ __align__(16) ULL    vbufP[L * H];  // [c][lane]: vertical pre-act PAIR
    __shared__ __align__(16) float  xrf[4][L];     // x rows as float (4-row ring)
    __shared__ __align__(16) float2 xpair[L];      // (x_r[c], x_{r+1}[c+DIR]) for current row
    __shared__ __align__(16) float  dws[H];

    const int lane = threadIdx.x;
    const int sample = blockIdx.x;

    // ---- per-lane weights (recurrence weights pre-scaled by log2e) ----
    const float win0 = Win[0 * H + lane] * LOG2E;
    const float win1 = Win[1 * H + lane] * LOG2E;
    const float win2 = Win[2 * H + lane] * LOG2E;
    const float win3 = Win[3 * H + lane] * LOG2E;
    const float d01  = win1 - win0;
    const float d23  = win3 - win2;
    const float bv   = bV[lane] * LOG2E;
    const float dwsl = Wout[lane * 2 + 0] - Wout[lane * 2 + 1];
    dws[lane] = dwsl;

    ULL wch[16], wcv[16];
    float rowsumH = 0.f, rowsumV = 0.f;
    #pragma unroll
    for (int k = 0; k < 16; k++) {
        const float h0 = WcH[(2 * k) * H + lane] * LOG2E;
        const float h1 = WcH[(2 * k + 1) * H + lane] * LOG2E;
        const float v0 = WcV[(2 * k) * H + lane] * LOG2E;
        const float v1 = WcV[(2 * k + 1) * H + lane] * LOG2E;
        wch[k] = pack2(h0, h1);
        wcv[k] = pack2(v0, v1);
        rowsumH += h0 + h1;
        rowsumV += v0 + v1;
    }
    float sdws = dwsl;
    #pragma unroll
    for (int off = 16; off; off >>= 1)
        sdws += __shfl_xor_sync(FULLMASK, sdws, off);
    const float dbo = (bout[0] - bout[1]) - sdws;    // head bias with h'=h+1 fold

    // Folded produce bases (x-independent parts pre-added):
    const float cbase_main = bv - rowsumV - rowsumH + win0 + win2;
    const float cbase_epi  = bv - rowsumV + win2;

    const int* xs = x + (long)sample * (L * L);

    // ---- preamble: rows 0 and 1 into the ring ----
    xrf[0][lane]      = (float)xs[lane];
    xrf[0][lane + 32] = (float)xs[lane + 32];
    xrf[1][lane]      = (float)xs[L + lane];
    xrf[1][lane + 32] = (float)xs[L + lane + 32];
    __syncwarp();
    // xpair for row 0 (DIR = +1): (x0[c], x1[min(c+1,63)])
    #pragma unroll
    for (int t = 0; t < 2; t++) {
        const int c = lane + 32 * t;
        const int cn = (c < 63) ? c + 1 : 63;
        xpair[c] = make_float2(xrf[0][c], xrf[1][cn]);
    }
    // vbuf row 0 (cV = 0, stateV = 0)
    vbufP[lane] = pack2(bv, 0.f);                      // c = 0: no WcH fold
    {
        const float b0 = bv - rowsumH + win0;
        #pragma unroll 4
        for (int c = 1; c < L; c++)
            vbufP[(c << 5) + lane] = pack2(fmaf(xrf[0][c - 1], d01, b0), 0.f);
    }
    __syncwarp();

    ULL hA[16], hB[16];
    float logacc = 0.f;
    int c0 = 0, dir = 1;

    for (int r = 0; r < L; r++) {
        // Load row r+2 into the ring (consumed at this row's END by the xpair
        // build -> LDG latency fully hidden under the 64-step scan).
        if (r + 2 < L) {
            const int s = (r + 2) & 3;
            xrf[s][lane]      = (float)xs[(r + 2) * L + lane];
            xrf[s][lane + 32] = (float)xs[(r + 2) * L + lane + 32];
        }
        const float* xcur = xrf[r & 3];

        auto rowbody = [&](const int DIR) {
            float* hcol = hrow + (c0 << 5);
            ULL*   vwr  = vbufP + (c0 << 5) + lane;               // produce write
            const ULL* vrd = vbufP + ((c0 + 2 * DIR) << 5) + lane;// vpre prefetch
            const float2* xp = xpair + c0 + DIR;                  // pair prefetch

            // ---- step 0 (no horizontal carry): h'(c0) into hA ----
            {
                float lo, hi; unpack2(vwr[0], lo, hi);
                const float h = eluP1(lo + hi);
                hcol[lane] = h;
                const ulonglong2* hp = reinterpret_cast<const ulonglong2*>(hcol);
                #pragma unroll
                for (int k = 0; k < 8; k++) {
                    ulonglong2 v = hp[k];
                    hA[2 * k] = v.x; hA[2 * k + 1] = v.y;
                }
            }
            ULL vpre = *(vbufP + ((c0 + DIR) << 5) + lane);
            float2 xcn = xpair[c0];    // (xc, xn) for produce(c0)

            // ---- fused step: h'(cn) from hOld; produce(c) from hOld ----
            auto fused = [&](ULL* hOld, ULL* hNew, const bool PF) {
                float* hc = hcol + DIR * H;
                // WcH matvec seeded by the vpre pair (2 chains)
                ULL a0 = vpre, a1 = 0ull;
                #pragma unroll
                for (int k = 0; k < 16; k += 2) {
                    a0 = ffma2(hOld[k + 0], wch[k + 0], a0);
                    a1 = ffma2(hOld[k + 1], wch[k + 1], a1);
                }
                a0 = fadd2(a0, a1);
                float lo, hi; unpack2(a0, lo, hi);
                const float h = eluP1(lo + hi);
                hc[lane] = h;
                // LDS burst immediately (same-warp STS->LDS order, no sync)
                {
                    const ulonglong2* hp = reinterpret_cast<const ulonglong2*>(hc);
                    #pragma unroll
                    for (int k = 0; k < 8; k++) {
                        ulonglong2 v = hp[k];
                        hNew[2 * k] = v.x; hNew[2 * k + 1] = v.y;
                    }
                }
                // prefetches (fill the load window)
                ULL vpre2 = 0ull;
                if (PF) { vpre2 = *vrd; vrd += DIR * H; }
                const float2 xcn2 = *xp; xp += DIR;

                // produce(c) on hOld: rsum via FMA-selects, 2 chains, pair store
                const float rsum = fmaf(xcn.x, d23, fmaf(xcn.y, d01, cbase_main));
                ULL v0 = pack2(rsum, 0.f), v1 = 0ull;
                #pragma unroll
                for (int k = 0; k < 16; k += 2) {
                    v0 = ffma2(hOld[k + 0], wcv[k + 0], v0);
                    v1 = ffma2(hOld[k + 1], wcv[k + 1], v1);
                }
                *vwr = fadd2(v0, v1);
                vwr += DIR * H;

                if (PF) vpre = vpre2;
                xcn = xcn2;
                hcol = hc;
            };

            #pragma unroll 2
            for (int j = 0; j < 31; j++) {
                fused(hA, hB, true);
                fused(hB, hA, true);
            }
            fused(hA, hB, false);       // final: vpre prefetch would be OOB

            // ---- epilogue: produce(c_last) — next row's start seed (no stateH) ----
            {
                const float rsum = fmaf(xcn.x, d23, cbase_epi);
                ULL v0 = pack2(rsum, 0.f), v1 = 0ull;
                #pragma unroll
                for (int k = 0; k < 16; k += 2) {
                    v0 = ffma2(hB[k + 0], wcv[k + 0], v0);
                    v1 = ffma2(hB[k + 1], wcv[k + 1], v1);
                }
                *vwr = fadd2(v0, v1);
            }
        };

        if (dir > 0) rowbody(1); else rowbody(-1);

        // ---- row-batched output head: lane handles columns lane, lane+32 ----
        #pragma unroll
        for (int t = 0; t < 2; t++) {
            const int cc = lane + 32 * t;
            const ulonglong2* hcolp = reinterpret_cast<const ulonglong2*>(hrow + (cc << 5));
            const ulonglong2* dwp   = reinterpret_cast<const ulonglong2*>(dws);
            ULL q0 = 0ull, q1 = 0ull;
            #pragma unroll
            for (int k = 0; k < 8; k++) {
                const int kk = (k + lane) & 7;   // bank-rotate
                ulonglong2 hv = hcolp[kk];
                ulonglong2 dv = dwp[kk];
                q0 = ffma2(hv.x, dv.x, q0);
                q1 = ffma2(hv.y, dv.y, q1);
            }
            q0 = fadd2(q0, q1);
            float lo, hi; unpack2(q0, lo, hi);
            const float q = lo + hi + dbo;
            const float tt = (xcur[cc] > 0.5f) ? q : -q;
            logacc -= fmaxf(tt, 0.f) + __logf(1.f + __expf(-fabsf(tt)));
        }

        // ---- build xpair for row r+1 (direction -dir); x_{r+2} loaded above ----
        if (r + 1 < L) {
            const float* xn1 = xrf[(r + 1) & 3];
            const float* xn2 = xrf[(r + 2) & 3];   // stale if r+2 >= L: value unused downstream
            const int DIRN = -dir;
            #pragma unroll
            for (int t = 0; t < 2; t++) {
                const int c = lane + 32 * t;
                int cn = c + DIRN;
                cn = (cn < 0) ? 0 : ((cn > 63) ? 63 : cn);
                xpair[c] = make_float2(xn1[c], xn2[cn]);
            }
        }

        c0 += 63 * dir;     // snake: next row starts where this one ended
        dir = -dir;
    }

    #pragma unroll
    for (int off = 16; off; off >>= 1)
        logacc += __shfl_xor_sync(FULLMASK, logacc, off);
    if (lane == 0) out[sample] = 0.5f * logacc;
}

extern "C" void kernel_launch(void* const* d_in, const int* in_sizes, int n_in,
                              void* d_out, int out_size)
{
    const int*   x    = (const int*)  d_in[0];
    const float* Win  = (const float*)d_in[1];
    const float* WcH  = (const float*)d_in[2];
    const float* WcV  = (const float*)d_in[3];
    const float* bV   = (const float*)d_in[4];
    const float* Wout = (const float*)d_in[5];
    const float* bout = (const float*)d_in[6];
    float* out = (float*)d_out;

    rnn2d_kernel<<<B, 32>>>(x, Win, WcH, WcV, bV, Wout, bout, out);
}